// round 1
// baseline (speedup 1.0000x reference)
#include <cuda_runtime.h>

// Shapes (fixed by the problem)
#define BB 256
#define NN 16
#define OBS 64
#define ACT 8
#define DD 128
#define HH 64
#define II 72       // OBS + ACT
#define NF 192      // OBS + D

// Padded shared-memory strides (bank-conflict free)
#define WE_S 73
#define W1_S 193
#define ST_S 65
#define AC_S 9
#define E_S  129
#define WT_S 17
#define UV_S 65

struct SmemLayout {
    float We[DD * WE_S];     // W_emb padded [128][73]
    float Wa[2 * DD];        // W_att [256]
    float W1[HH * W1_S];     // W1 padded [64][193]
    float W2[HH];            // W2 [64]
    float st[NN * ST_S];     // states [16][65]
    float ac[NN * AC_S];     // actions [16][9]
    float po[NN * AC_S];     // policies [16][9]
    float emba[NN * E_S];    // pre-tanh emb of obs_actions
    float ta[NN * E_S];      // tanh(emb_a)
    float de[NN * E_S];      // tanh(emb_p) - tanh(emb_a)
    float S[NN * E_S];       // w @ ta
    float w[NN * WT_S];      // softmax weights [16][17]
    float U[NN * UV_S];      // [16][65]
    float V[NN * UV_S];
    float ssrc[NN];
    float sdst[NN];
};

__device__ __forceinline__ float lrelu(float x) {
    return x > 0.0f ? x : 0.01f * x;
}

__global__ void __launch_bounds__(256, 1)
gac_kernel(const float* __restrict__ g_st, const float* __restrict__ g_po,
           const float* __restrict__ g_ac, const float* __restrict__ g_We,
           const float* __restrict__ g_Wa, const float* __restrict__ g_W1,
           const float* __restrict__ g_W2, float* __restrict__ out,
           int write_w)
{
    extern __shared__ float smem_raw[];
    SmemLayout& s = *reinterpret_cast<SmemLayout*>(smem_raw);
    const int t = threadIdx.x;
    const int b = blockIdx.x;

    // ---- cooperative loads (weights + per-batch inputs) ----
    for (int idx = t; idx < DD * II; idx += 256) {
        int r = idx / II, c = idx - r * II;
        s.We[r * WE_S + c] = g_We[idx];
    }
    for (int idx = t; idx < 2 * DD; idx += 256) s.Wa[idx] = g_Wa[idx];
    for (int idx = t; idx < HH * NF; idx += 256) {
        int r = idx / NF, c = idx - r * NF;
        s.W1[r * W1_S + c] = g_W1[idx];
    }
    if (t < HH) s.W2[t] = g_W2[t];
    for (int idx = t; idx < NN * OBS; idx += 256) {
        int r = idx >> 6, c = idx & 63;
        s.st[r * ST_S + c] = g_st[b * NN * OBS + idx];
    }
    if (t < NN * ACT) {
        int r = t >> 3, c = t & 7;
        s.ac[r * AC_S + c] = g_ac[b * NN * ACT + t];
        s.po[r * AC_S + c] = g_po[b * NN * ACT + t];
    }
    __syncthreads();

    // ---- embeddings: emb_a (pre-tanh), tanh, delta ----
    {
        const int n = t & 15, d0 = (t >> 4) * 8;
        float sa[8], sp[8];
        #pragma unroll
        for (int u = 0; u < 8; u++) sa[u] = 0.0f;
        // shared obs part
        #pragma unroll 4
        for (int k = 0; k < OBS; k++) {
            float x = s.st[n * ST_S + k];
            #pragma unroll
            for (int u = 0; u < 8; u++)
                sa[u] = fmaf(s.We[(d0 + u) * WE_S + k], x, sa[u]);
        }
        #pragma unroll
        for (int u = 0; u < 8; u++) sp[u] = sa[u];
        #pragma unroll
        for (int k = 0; k < ACT; k++) {
            float xa = s.ac[n * AC_S + k];
            float xp = s.po[n * AC_S + k];
            #pragma unroll
            for (int u = 0; u < 8; u++) {
                float wv = s.We[(d0 + u) * WE_S + OBS + k];
                sa[u] = fmaf(wv, xa, sa[u]);
                sp[u] = fmaf(wv, xp, sp[u]);
            }
        }
        #pragma unroll
        for (int u = 0; u < 8; u++) {
            float e = sa[u];
            float th = tanhf(e);
            s.emba[n * E_S + d0 + u] = e;
            s.ta[n * E_S + d0 + u] = th;
            s.de[n * E_S + d0 + u] = tanhf(sp[u]) - th;
        }
    }
    __syncthreads();

    // ---- attention scalars s_src/s_dst (one warp per 2 rows) ----
    {
        const int wid = t >> 5, lane = t & 31;
        for (int n = wid; n < NN; n += 8) {
            float a = 0.0f, bv = 0.0f;
            #pragma unroll
            for (int q = 0; q < 4; q++) {
                int d = lane + q * 32;
                float e = s.emba[n * E_S + d];
                a  = fmaf(e, s.Wa[d], a);
                bv = fmaf(e, s.Wa[DD + d], bv);
            }
            #pragma unroll
            for (int off = 16; off; off >>= 1) {
                a  += __shfl_xor_sync(0xffffffffu, a, off);
                bv += __shfl_xor_sync(0xffffffffu, bv, off);
            }
            if (lane == 0) { s.ssrc[n] = a; s.sdst[n] = bv; }
        }
    }
    __syncthreads();

    // ---- softmax over j of leaky_relu(s_src[i] + s_dst[j]) ----
    if (t < NN) {
        const int i = t;
        float si = s.ssrc[i];
        float sc[NN];
        float mx = -1e30f;
        #pragma unroll
        for (int j = 0; j < NN; j++) {
            float v = lrelu(si + s.sdst[j]);
            sc[j] = v;
            mx = fmaxf(mx, v);
        }
        float sum = 0.0f;
        #pragma unroll
        for (int j = 0; j < NN; j++) {
            float e = expf(sc[j] - mx);
            sc[j] = e;
            sum += e;
        }
        float inv = 1.0f / sum;
        #pragma unroll
        for (int j = 0; j < NN; j++) s.w[i * WT_S + j] = sc[j] * inv;
    }
    __syncthreads();

    // ---- emit ret_weight + compute S = w @ ta ----
    if (write_w) {
        int wi = t >> 4, wj = t & 15;
        out[BB * NN * NN + b * NN * NN + t] = s.w[wi * WT_S + wj];
    }
    {
        const int i = t & 15, d0 = (t >> 4) * 8;
        float acc[8];
        #pragma unroll
        for (int u = 0; u < 8; u++) acc[u] = 0.0f;
        #pragma unroll
        for (int j = 0; j < NN; j++) {
            float wv = s.w[i * WT_S + j];
            #pragma unroll
            for (int u = 0; u < 8; u++)
                acc[u] = fmaf(wv, s.ta[j * E_S + d0 + u], acc[u]);
        }
        #pragma unroll
        for (int u = 0; u < 8; u++) s.S[i * E_S + d0 + u] = acc[u];
    }
    __syncthreads();

    // ---- U[i,h] = W1s@states[i] + W1d@(S[i]/16); V[i,h] = W1d@(de[i]/16) ----
    {
        const int i = t & 15, h0 = (t >> 4) * 4;
        float ua[4], va[4];
        #pragma unroll
        for (int u = 0; u < 4; u++) { ua[u] = 0.0f; va[u] = 0.0f; }
        #pragma unroll 4
        for (int k = 0; k < OBS; k++) {
            float x = s.st[i * ST_S + k];
            #pragma unroll
            for (int u = 0; u < 4; u++)
                ua[u] = fmaf(s.W1[(h0 + u) * W1_S + k], x, ua[u]);
        }
        const float invN = 1.0f / 16.0f;
        #pragma unroll 4
        for (int d = 0; d < DD; d++) {
            float xs = s.S[i * E_S + d] * invN;
            float xd = s.de[i * E_S + d] * invN;
            #pragma unroll
            for (int u = 0; u < 4; u++) {
                float wv = s.W1[(h0 + u) * W1_S + OBS + d];
                ua[u] = fmaf(wv, xs, ua[u]);
                va[u] = fmaf(wv, xd, va[u]);
            }
        }
        #pragma unroll
        for (int u = 0; u < 4; u++) {
            s.U[i * UV_S + h0 + u] = ua[u];
            s.V[i * UV_S + h0 + u] = va[u];
        }
    }
    __syncthreads();

    // ---- value[b,i,j] = W2 . lrelu(U[i] + w[i,j]*V[j]) ----
    {
        const int i = t >> 4, j = t & 15;
        float wv = s.w[i * WT_S + j];
        float acc = 0.0f;
        #pragma unroll
        for (int h = 0; h < HH; h++) {
            float hv = fmaf(wv, s.V[j * UV_S + h], s.U[i * UV_S + h]);
            acc = fmaf(s.W2[h], lrelu(hv), acc);
        }
        out[b * NN * NN + t] = acc;
    }
}

extern "C" void kernel_launch(void* const* d_in, const int* in_sizes, int n_in,
                              void* d_out, int out_size) {
    const float* st = (const float*)d_in[0];
    const float* po = (const float*)d_in[1];
    const float* ac = (const float*)d_in[2];
    const float* We = (const float*)d_in[3];
    const float* Wa = (const float*)d_in[4];
    const float* W1 = (const float*)d_in[5];
    const float* W2 = (const float*)d_in[6];
    float* out = (float*)d_out;

    const int smem = (int)sizeof(SmemLayout);
    cudaFuncSetAttribute(gac_kernel, cudaFuncAttributeMaxDynamicSharedMemorySize, smem);

    // out = [value (B*N*N), ret_weight (B*N*N)] if the harness concatenates the tuple
    int write_w = (out_size >= 2 * BB * NN * NN) ? 1 : 0;

    gac_kernel<<<BB, 256, smem>>>(st, po, ac, We, Wa, W1, W2, out, write_w);
}

// round 2
// speedup vs baseline: 1.2423x; 1.2423x over previous
#include <cuda_runtime.h>

// Shapes (fixed by the problem)
#define BB 256
#define NN 16
#define OBS 64
#define ACT 8
#define DD 128
#define HH 64
#define II 72       // OBS + ACT
#define NF 192      // OBS + D

// Padded strides
#define WE_S 73
#define W1_S 193
#define ST_S 65
#define AC_S 9
#define E_S  129
#define WT_S 17
#define HV_S 65

// float offsets into dynamic smem
#define OFF_WEU 0
#define SZ_WEU  (HH * W1_S)           /* 12352 > 128*73 = 9344 */
#define OFF_WA  (OFF_WEU + SZ_WEU)
#define OFF_W2  (OFF_WA + 2 * DD)
#define OFF_ST  (OFF_W2 + HH)
#define OFF_AC  (OFF_ST + NN * ST_S)
#define OFF_PO  (OFF_AC + NN * AC_S)
#define OFF_TA  (OFF_PO + NN * AC_S)
#define OFF_DE  (OFF_TA + NN * E_S)
#define OFF_W   (OFF_DE + NN * E_S)
#define OFF_T   (OFF_W  + NN * WT_S)
#define OFF_V   (OFF_T  + NN * HV_S)
#define OFF_UST (OFF_V  + NN * HV_S)
#define OFF_U   (OFF_UST + NN * HV_S)
#define OFF_SSRC (OFF_U + NN * HV_S)
#define OFF_SDST (OFF_SSRC + NN)
#define SMEM_FLOATS (OFF_SDST + NN)

__device__ __forceinline__ float lrelu(float x) {
    return x > 0.0f ? x : 0.01f * x;
}

__global__ void __launch_bounds__(256, 2)
gac_kernel(const float* __restrict__ g_st, const float* __restrict__ g_po,
           const float* __restrict__ g_ac, const float* __restrict__ g_We,
           const float* __restrict__ g_Wa, const float* __restrict__ g_W1,
           const float* __restrict__ g_W2, float* __restrict__ out,
           int write_w)
{
    extern __shared__ float sm[];
    float* We  = sm + OFF_WEU;   // stride WE_S (phase 1)
    float* W1  = sm + OFF_WEU;   // stride W1_S (phase 3+, overwrites We)
    float* Wa  = sm + OFF_WA;
    float* W2s = sm + OFF_W2;
    float* st  = sm + OFF_ST;
    float* ac  = sm + OFF_AC;
    float* po  = sm + OFF_PO;
    float* ta  = sm + OFF_TA;
    float* de  = sm + OFF_DE;
    float* w   = sm + OFF_W;
    float* T   = sm + OFF_T;
    float* V   = sm + OFF_V;
    float* Ust = sm + OFF_UST;
    float* U   = sm + OFF_U;
    float* ssrc = sm + OFF_SSRC;
    float* sdst = sm + OFF_SDST;

    const int t = threadIdx.x;
    const int b = blockIdx.x;

    // ---- P0: cooperative loads ----
    for (int idx = t; idx < DD * II; idx += 256) {
        int r = idx / II, c = idx - r * II;
        We[r * WE_S + c] = g_We[idx];
    }
    if (t < 2 * DD) Wa[t] = g_Wa[t];
    if (t < HH) W2s[t] = g_W2[t];
    for (int idx = t; idx < NN * OBS; idx += 256) {
        int r = idx >> 6, c = idx & 63;
        st[r * ST_S + c] = g_st[b * NN * OBS + idx];
    }
    if (t < NN * ACT) {
        int r = t >> 3, c = t & 7;
        ac[r * AC_S + c] = g_ac[b * NN * ACT + t];
        po[r * AC_S + c] = g_po[b * NN * ACT + t];
    }
    if (t < NN) { ssrc[t] = 0.0f; sdst[t] = 0.0f; }
    __syncthreads();

    // ---- P1: embeddings (tanh + delta) and attention-scalar partials ----
    {
        const int n = t & 15, d0 = (t >> 4) * 8;
        float sa[8], sp[8];
        #pragma unroll
        for (int u = 0; u < 8; u++) sa[u] = 0.0f;
        #pragma unroll 4
        for (int k = 0; k < OBS; k++) {
            float x = st[n * ST_S + k];
            #pragma unroll
            for (int u = 0; u < 8; u++)
                sa[u] = fmaf(We[(d0 + u) * WE_S + k], x, sa[u]);
        }
        #pragma unroll
        for (int u = 0; u < 8; u++) sp[u] = sa[u];
        #pragma unroll
        for (int k = 0; k < ACT; k++) {
            float xa = ac[n * AC_S + k];
            float xp = po[n * AC_S + k];
            #pragma unroll
            for (int u = 0; u < 8; u++) {
                float wv = We[(d0 + u) * WE_S + OBS + k];
                sa[u] = fmaf(wv, xa, sa[u]);
                sp[u] = fmaf(wv, xp, sp[u]);
            }
        }
        float psrc = 0.0f, pdst = 0.0f;
        #pragma unroll
        for (int u = 0; u < 8; u++) {
            float e = sa[u];
            psrc = fmaf(e, Wa[d0 + u], psrc);
            pdst = fmaf(e, Wa[DD + d0 + u], pdst);
            float th = tanhf(e);
            ta[n * E_S + d0 + u] = th;
            de[n * E_S + d0 + u] = tanhf(sp[u]) - th;
        }
        atomicAdd(&ssrc[n], psrc);
        atomicAdd(&sdst[n], pdst);
    }
    __syncthreads();

    // ---- P2: softmax (t<16)  ||  load W1 into union region (t>=16) ----
    if (t < NN) {
        const int i = t;
        float si = ssrc[i];
        float sc[NN];
        float mx = -1e30f;
        #pragma unroll
        for (int j = 0; j < NN; j++) {
            float v = lrelu(si + sdst[j]);
            sc[j] = v;
            mx = fmaxf(mx, v);
        }
        float sum = 0.0f;
        #pragma unroll
        for (int j = 0; j < NN; j++) {
            float e = expf(sc[j] - mx);
            sc[j] = e;
            sum += e;
        }
        float inv = 1.0f / sum;
        #pragma unroll
        for (int j = 0; j < NN; j++) w[i * WT_S + j] = sc[j] * inv;
    } else {
        const int tt = t - 16;   // 240 loader threads
        for (int idx = tt; idx < HH * NF; idx += 240) {
            int r = idx / NF, c = idx - r * NF;
            W1[r * W1_S + c] = g_W1[idx];
        }
    }
    __syncthreads();

    // ret_weight store overlaps with P3 compute
    if (write_w)
        out[BB * NN * NN + b * NN * NN + t] = w[(t >> 4) * WT_S + (t & 15)];

    // ---- P3: T[j,h]=(W1d.ta[j])/16, V[j,h]=(W1d.de[j])/16, Ust[i,h]=W1s.st[i] ----
    {
        const int n = t & 15, h0 = (t >> 4) * 4;
        float at[4], av[4], au[4];
        #pragma unroll
        for (int u = 0; u < 4; u++) { at[u] = 0.0f; av[u] = 0.0f; au[u] = 0.0f; }
        #pragma unroll 4
        for (int k = 0; k < OBS; k++) {
            float x = st[n * ST_S + k];
            #pragma unroll
            for (int u = 0; u < 4; u++)
                au[u] = fmaf(W1[(h0 + u) * W1_S + k], x, au[u]);
        }
        #pragma unroll 4
        for (int d = 0; d < DD; d++) {
            float xt = ta[n * E_S + d];
            float xd = de[n * E_S + d];
            #pragma unroll
            for (int u = 0; u < 4; u++) {
                float wv = W1[(h0 + u) * W1_S + OBS + d];
                at[u] = fmaf(wv, xt, at[u]);
                av[u] = fmaf(wv, xd, av[u]);
            }
        }
        const float invN = 1.0f / 16.0f;
        #pragma unroll
        for (int u = 0; u < 4; u++) {
            T[n * HV_S + h0 + u]   = at[u] * invN;
            V[n * HV_S + h0 + u]   = av[u] * invN;
            Ust[n * HV_S + h0 + u] = au[u];
        }
    }
    __syncthreads();

    // ---- P4a: U[i,h] = Ust[i,h] + sum_j w[i,j] * T[j,h] ----
    {
        const int i = t & 15, h0 = (t >> 4) * 4;
        float acc[4];
        #pragma unroll
        for (int u = 0; u < 4; u++) acc[u] = Ust[i * HV_S + h0 + u];
        #pragma unroll
        for (int j = 0; j < NN; j++) {
            float wv = w[i * WT_S + j];
            #pragma unroll
            for (int u = 0; u < 4; u++)
                acc[u] = fmaf(wv, T[j * HV_S + h0 + u], acc[u]);
        }
        #pragma unroll
        for (int u = 0; u < 4; u++) U[i * HV_S + h0 + u] = acc[u];
    }
    __syncthreads();

    // ---- P4b: value[b,i,j] = W2 . lrelu(U[i] + w[i,j]*V[j]) ----
    {
        const int i = t >> 4, j = t & 15;
        float wv = w[i * WT_S + j];
        float acc = 0.0f;
        #pragma unroll
        for (int h = 0; h < HH; h++) {
            float hv = fmaf(wv, V[j * HV_S + h], U[i * HV_S + h]);
            acc = fmaf(W2s[h], lrelu(hv), acc);
        }
        out[b * NN * NN + t] = acc;
    }
}

extern "C" void kernel_launch(void* const* d_in, const int* in_sizes, int n_in,
                              void* d_out, int out_size) {
    const float* st = (const float*)d_in[0];
    const float* po = (const float*)d_in[1];
    const float* ac = (const float*)d_in[2];
    const float* We = (const float*)d_in[3];
    const float* Wa = (const float*)d_in[4];
    const float* W1 = (const float*)d_in[5];
    const float* W2 = (const float*)d_in[6];
    float* out = (float*)d_out;

    const int smem = SMEM_FLOATS * (int)sizeof(float);
    cudaFuncSetAttribute(gac_kernel, cudaFuncAttributeMaxDynamicSharedMemorySize, smem);

    int write_w = (out_size >= 2 * BB * NN * NN) ? 1 : 0;

    gac_kernel<<<BB, 256, smem>>>(st, po, ac, We, Wa, W1, W2, out, write_w);
}

// round 3
// speedup vs baseline: 1.4780x; 1.1897x over previous
#include <cuda_runtime.h>

// Shapes (fixed)
#define BB 256
#define NN 16
#define OBS 64
#define ACT 8
#define DD 128
#define HH 64
#define II 72
#define NF 192

// 16B-aligned padded strides (floats)
#define WE_S 76
#define W1_S 196
#define ST_S 68
#define AC_S 12
#define E_S  132
#define WT_S 17
#define HV_S 68

// float offsets into dynamic smem (all float4-aligned)
#define OFF_WEU 0
#define SZ_WEU  12544                 /* max(128*76=9728, 64*196=12544) */
#define OFF_WA  (OFF_WEU + SZ_WEU)    /* 12544 */
#define OFF_W2  (OFF_WA + 2 * DD)     /* 12800 */
#define OFF_ST  (OFF_W2 + HH)         /* 12864 */
#define OFF_AC  (OFF_ST + NN * ST_S)  /* 13952 */
#define OFF_PO  (OFF_AC + NN * AC_S)  /* 14144 */
#define OFF_TA  (OFF_PO + NN * AC_S)  /* 14336 */
#define OFF_DE  (OFF_TA + NN * E_S)   /* 16448 */
#define OFF_W   (OFF_DE + NN * E_S)   /* 18560 */
#define OFF_T   (OFF_W  + NN * WT_S)  /* 18832 */
#define OFF_V   (OFF_T  + NN * HV_S)  /* 19920 */
#define OFF_U   (OFF_V  + NN * HV_S)  /* 21008 */
#define OFF_SSRC (OFF_U + NN * HV_S)  /* 22096 */
#define OFF_SDST (OFF_SSRC + NN)      /* 22112 */
#define SMEM_FLOATS (OFF_SDST + NN)   /* 22128 -> 88512 B */

__device__ __forceinline__ float lrelu(float x) {
    return x > 0.0f ? x : 0.01f * x;
}

// accurate-enough fast tanh (~1e-6 rel err), branch-free
__device__ __forceinline__ float fast_tanh(float x) {
    float cx = fminf(fmaxf(x, -10.0f), 10.0f);
    float e = __expf(2.0f * cx);
    return __fdividef(e - 1.0f, e + 1.0f);
}

__global__ void __launch_bounds__(256, 2)
gac_kernel(const float* __restrict__ g_st, const float* __restrict__ g_po,
           const float* __restrict__ g_ac, const float* __restrict__ g_We,
           const float* __restrict__ g_Wa, const float* __restrict__ g_W1,
           const float* __restrict__ g_W2, float* __restrict__ out,
           int write_w)
{
    extern __shared__ float sm[];
    float* We  = sm + OFF_WEU;   // [128][76] phase 1
    float* W1  = sm + OFF_WEU;   // [64][196] phase 3+ (union, overwrites We)
    float* Wa  = sm + OFF_WA;
    float* W2s = sm + OFF_W2;
    float* st  = sm + OFF_ST;
    float* ac  = sm + OFF_AC;
    float* po  = sm + OFF_PO;
    float* ta  = sm + OFF_TA;
    float* de  = sm + OFF_DE;
    float* w   = sm + OFF_W;
    float* T   = sm + OFF_T;
    float* V   = sm + OFF_V;
    float* U   = sm + OFF_U;
    float* ssrc = sm + OFF_SSRC;
    float* sdst = sm + OFF_SDST;

    const int t = threadIdx.x;
    const int b = blockIdx.x;

    // ---- P0: cooperative loads ----
    for (int idx = t; idx < DD * II; idx += 256) {
        int r = idx / II, c = idx - r * II;
        We[r * WE_S + c] = g_We[idx];
    }
    if (t < 2 * DD) Wa[t] = g_Wa[t];
    if (t < HH) W2s[t] = g_W2[t];
    for (int idx = t; idx < NN * OBS; idx += 256) {
        int r = idx >> 6, c = idx & 63;
        st[r * ST_S + c] = g_st[b * NN * OBS + idx];
    }
    if (t < NN * ACT) {
        int r = t >> 3, c = t & 7;
        ac[r * AC_S + c] = g_ac[b * NN * ACT + t];
        po[r * AC_S + c] = g_po[b * NN * ACT + t];
    }
    if (t < NN) { ssrc[t] = 0.0f; sdst[t] = 0.0f; }
    __syncthreads();

    // ---- P1: embeddings (tanh + delta) and attention-scalar partials ----
    {
        const int n = t & 15, d0 = (t >> 4) * 8;
        float sa[8], sp[8];
        #pragma unroll
        for (int u = 0; u < 8; u++) sa[u] = 0.0f;
        #pragma unroll
        for (int k = 0; k < OBS; k += 4) {
            float4 x = *(const float4*)&st[n * ST_S + k];
            #pragma unroll
            for (int u = 0; u < 8; u++) {
                float4 wv = *(const float4*)&We[(d0 + u) * WE_S + k];
                sa[u] = fmaf(wv.x, x.x, sa[u]);
                sa[u] = fmaf(wv.y, x.y, sa[u]);
                sa[u] = fmaf(wv.z, x.z, sa[u]);
                sa[u] = fmaf(wv.w, x.w, sa[u]);
            }
        }
        #pragma unroll
        for (int u = 0; u < 8; u++) sp[u] = sa[u];
        #pragma unroll
        for (int k = 0; k < ACT; k += 4) {
            float4 xa = *(const float4*)&ac[n * AC_S + k];
            float4 xp = *(const float4*)&po[n * AC_S + k];
            #pragma unroll
            for (int u = 0; u < 8; u++) {
                float4 wv = *(const float4*)&We[(d0 + u) * WE_S + OBS + k];
                sa[u] = fmaf(wv.x, xa.x, sa[u]);
                sa[u] = fmaf(wv.y, xa.y, sa[u]);
                sa[u] = fmaf(wv.z, xa.z, sa[u]);
                sa[u] = fmaf(wv.w, xa.w, sa[u]);
                sp[u] = fmaf(wv.x, xp.x, sp[u]);
                sp[u] = fmaf(wv.y, xp.y, sp[u]);
                sp[u] = fmaf(wv.z, xp.z, sp[u]);
                sp[u] = fmaf(wv.w, xp.w, sp[u]);
            }
        }
        float psrc = 0.0f, pdst = 0.0f;
        #pragma unroll
        for (int u = 0; u < 8; u++) {
            float e = sa[u];
            psrc = fmaf(e, Wa[d0 + u], psrc);
            pdst = fmaf(e, Wa[DD + d0 + u], pdst);
            float th = fast_tanh(e);
            ta[n * E_S + d0 + u] = th;
            de[n * E_S + d0 + u] = fast_tanh(sp[u]) - th;
        }
        atomicAdd(&ssrc[n], psrc);
        atomicAdd(&sdst[n], pdst);
    }
    __syncthreads();

    // ---- P2: softmax (t<16)  ||  load W1 into union region (t>=16) ----
    if (t < NN) {
        const int i = t;
        float si = ssrc[i];
        float sc[NN];
        float mx = -1e30f;
        #pragma unroll
        for (int j = 0; j < NN; j++) {
            float v = lrelu(si + sdst[j]);
            sc[j] = v;
            mx = fmaxf(mx, v);
        }
        float sum = 0.0f;
        #pragma unroll
        for (int j = 0; j < NN; j++) {
            float e = __expf(sc[j] - mx);
            sc[j] = e;
            sum += e;
        }
        float inv = 1.0f / sum;
        #pragma unroll
        for (int j = 0; j < NN; j++) w[i * WT_S + j] = sc[j] * inv;
    } else {
        const int tt = t - 16;   // 240 loader threads
        for (int idx = tt; idx < HH * NF; idx += 240) {
            int r = idx / NF, c = idx - r * NF;
            W1[r * W1_S + c] = g_W1[idx];
        }
    }
    __syncthreads();

    // ret_weight store overlaps with P3 compute
    if (write_w)
        out[BB * NN * NN + b * NN * NN + t] = w[(t >> 4) * WT_S + (t & 15)];

    // ---- P3: T[n,h]=(W1d.ta[n])/16, V[n,h]=(W1d.de[n])/16, au=W1s.st[n] (regs) ----
    const int pn = t & 15, ph0 = (t >> 4) * 4;
    float au[4];
    {
        float at[4], av[4];
        #pragma unroll
        for (int u = 0; u < 4; u++) { at[u] = 0.0f; av[u] = 0.0f; au[u] = 0.0f; }
        #pragma unroll
        for (int k = 0; k < OBS; k += 4) {
            float4 x = *(const float4*)&st[pn * ST_S + k];
            #pragma unroll
            for (int u = 0; u < 4; u++) {
                float4 wv = *(const float4*)&W1[(ph0 + u) * W1_S + k];
                au[u] = fmaf(wv.x, x.x, au[u]);
                au[u] = fmaf(wv.y, x.y, au[u]);
                au[u] = fmaf(wv.z, x.z, au[u]);
                au[u] = fmaf(wv.w, x.w, au[u]);
            }
        }
        #pragma unroll
        for (int d = 0; d < DD; d += 4) {
            float4 xt = *(const float4*)&ta[pn * E_S + d];
            float4 xd = *(const float4*)&de[pn * E_S + d];
            #pragma unroll
            for (int u = 0; u < 4; u++) {
                float4 wv = *(const float4*)&W1[(ph0 + u) * W1_S + OBS + d];
                at[u] = fmaf(wv.x, xt.x, at[u]);
                at[u] = fmaf(wv.y, xt.y, at[u]);
                at[u] = fmaf(wv.z, xt.z, at[u]);
                at[u] = fmaf(wv.w, xt.w, at[u]);
                av[u] = fmaf(wv.x, xd.x, av[u]);
                av[u] = fmaf(wv.y, xd.y, av[u]);
                av[u] = fmaf(wv.z, xd.z, av[u]);
                av[u] = fmaf(wv.w, xd.w, av[u]);
            }
        }
        const float invN = 1.0f / 16.0f;
        float4 tv, vv;
        tv.x = at[0] * invN; tv.y = at[1] * invN; tv.z = at[2] * invN; tv.w = at[3] * invN;
        vv.x = av[0] * invN; vv.y = av[1] * invN; vv.z = av[2] * invN; vv.w = av[3] * invN;
        *(float4*)&T[pn * HV_S + ph0] = tv;
        *(float4*)&V[pn * HV_S + ph0] = vv;
    }
    __syncthreads();

    // ---- P4a: U[n,h] = au + sum_j w[n,j] * T[j,h]  (au register-carried) ----
    {
        float acc[4];
        #pragma unroll
        for (int u = 0; u < 4; u++) acc[u] = au[u];
        #pragma unroll
        for (int j = 0; j < NN; j++) {
            float wv = w[pn * WT_S + j];
            float4 tv = *(const float4*)&T[j * HV_S + ph0];
            acc[0] = fmaf(wv, tv.x, acc[0]);
            acc[1] = fmaf(wv, tv.y, acc[1]);
            acc[2] = fmaf(wv, tv.z, acc[2]);
            acc[3] = fmaf(wv, tv.w, acc[3]);
        }
        float4 uv;
        uv.x = acc[0]; uv.y = acc[1]; uv.z = acc[2]; uv.w = acc[3];
        *(float4*)&U[pn * HV_S + ph0] = uv;
    }
    __syncthreads();

    // ---- P4b: value[b,i,j] = W2 . lrelu(U[i] + w[i,j]*V[j]) ----
    {
        const int i = t >> 4, j = t & 15;
        float wv = w[i * WT_S + j];
        float acc = 0.0f;
        #pragma unroll
        for (int h = 0; h < HH; h += 4) {
            float4 u4 = *(const float4*)&U[i * HV_S + h];
            float4 v4 = *(const float4*)&V[j * HV_S + h];
            float4 w2 = *(const float4*)&W2s[h];
            acc = fmaf(w2.x, lrelu(fmaf(wv, v4.x, u4.x)), acc);
            acc = fmaf(w2.y, lrelu(fmaf(wv, v4.y, u4.y)), acc);
            acc = fmaf(w2.z, lrelu(fmaf(wv, v4.z, u4.z)), acc);
            acc = fmaf(w2.w, lrelu(fmaf(wv, v4.w, u4.w)), acc);
        }
        out[b * NN * NN + t] = acc;
    }
}

extern "C" void kernel_launch(void* const* d_in, const int* in_sizes, int n_in,
                              void* d_out, int out_size) {
    const float* st = (const float*)d_in[0];
    const float* po = (const float*)d_in[1];
    const float* ac = (const float*)d_in[2];
    const float* We = (const float*)d_in[3];
    const float* Wa = (const float*)d_in[4];
    const float* W1 = (const float*)d_in[5];
    const float* W2 = (const float*)d_in[6];
    float* out = (float*)d_out;

    const int smem = SMEM_FLOATS * (int)sizeof(float);
    cudaFuncSetAttribute(gac_kernel, cudaFuncAttributeMaxDynamicSharedMemorySize, smem);

    int write_w = (out_size >= 2 * BB * NN * NN) ? 1 : 0;

    gac_kernel<<<BB, 256, smem>>>(st, po, ac, We, Wa, W1, W2, out, write_w);
}

// round 4
// speedup vs baseline: 1.6453x; 1.1132x over previous
#include <cuda_runtime.h>

// Shapes (fixed)
#define BB 256
#define NN 16
#define OBS 64
#define ACT 8
#define DD 128
#define HH 64
#define II 72
#define NF 192

// 16B-aligned padded strides (floats)
#define WE_S 76
#define W1_S 196
#define ST_S 68
#define AC_S 12
#define E_S  132
#define WT_S 17
#define HV_S 68

// float offsets into dynamic smem (all float4-aligned)
#define OFF_WEU 0
#define SZ_WEU  12544                 /* max(128*76=9728, 64*196=12544) */
#define OFF_WA  (OFF_WEU + SZ_WEU)
#define OFF_W2  (OFF_WA + 2 * DD)
#define OFF_ST  (OFF_W2 + HH)
#define OFF_AC  (OFF_ST + NN * ST_S)
#define OFF_PO  (OFF_AC + NN * AC_S)
#define OFF_TA  (OFF_PO + NN * AC_S)
#define OFF_DE  (OFF_TA + NN * E_S)
#define OFF_W   (OFF_DE + NN * E_S)
#define OFF_T   (OFF_W  + NN * WT_S)
#define OFF_V   (OFF_T  + NN * HV_S)
#define OFF_U   (OFF_V  + NN * HV_S)
#define OFF_SSRC (OFF_U + NN * HV_S)
#define OFF_SDST (OFF_SSRC + NN)
#define SMEM_FLOATS (OFF_SDST + NN)

__device__ __forceinline__ float lrelu(float x) {
    return x > 0.0f ? x : 0.01f * x;
}

__device__ __forceinline__ float fast_tanh(float x) {
    float cx = fminf(fmaxf(x, -10.0f), 10.0f);
    float e = __expf(2.0f * cx);
    return __fdividef(e - 1.0f, e + 1.0f);
}

__device__ __forceinline__ float dot4(float4 a, float4 b, float acc) {
    acc = fmaf(a.x, b.x, acc);
    acc = fmaf(a.y, b.y, acc);
    acc = fmaf(a.z, b.z, acc);
    acc = fmaf(a.w, b.w, acc);
    return acc;
}

__global__ void __launch_bounds__(256, 2)
gac_kernel(const float* __restrict__ g_st, const float* __restrict__ g_po,
           const float* __restrict__ g_ac, const float* __restrict__ g_We,
           const float* __restrict__ g_Wa, const float* __restrict__ g_W1,
           const float* __restrict__ g_W2, float* __restrict__ out,
           int write_w)
{
    extern __shared__ float sm[];
    float* We  = sm + OFF_WEU;   // [128][76] phase 1
    float* W1  = sm + OFF_WEU;   // [64][196] phase 3+ (union)
    float* Wa  = sm + OFF_WA;
    float* W2s = sm + OFF_W2;
    float* st  = sm + OFF_ST;
    float* ac  = sm + OFF_AC;
    float* po  = sm + OFF_PO;
    float* ta  = sm + OFF_TA;
    float* de  = sm + OFF_DE;
    float* w   = sm + OFF_W;
    float* T   = sm + OFF_T;
    float* V   = sm + OFF_V;
    float* U   = sm + OFF_U;
    float* ssrc = sm + OFF_SSRC;
    float* sdst = sm + OFF_SDST;

    const int t = threadIdx.x;
    const int b = blockIdx.x;

    // ---- P0: cooperative float4 loads ----
    {
        // We: 128x72 = 2304 float4, 9 per thread
        #pragma unroll
        for (int i = 0; i < 9; i++) {
            int e = (t + i * 256) * 4;
            int r = e / II, c = e - r * II;
            float4 v = *(const float4*)&g_We[e];
            *(float4*)&We[r * WE_S + c] = v;
        }
        if (t < 64) *(float4*)&Wa[t * 4] = *(const float4*)&g_Wa[t * 4];
        if (t < 16) *(float4*)&W2s[t * 4] = *(const float4*)&g_W2[t * 4];
        // states: 16x64 = 256 float4, 1 per thread
        {
            int r = t >> 4, c = (t & 15) * 4;
            *(float4*)&st[r * ST_S + c] = *(const float4*)&g_st[b * NN * OBS + t * 4];
        }
        // actions/policies: 16x8 = 32 float4 each
        if (t < 32) {
            int r = t >> 1, c = (t & 1) * 4;
            *(float4*)&ac[r * AC_S + c] = *(const float4*)&g_ac[b * NN * ACT + t * 4];
            *(float4*)&po[r * AC_S + c] = *(const float4*)&g_po[b * NN * ACT + t * 4];
        }
        if (t < NN) { ssrc[t] = 0.0f; sdst[t] = 0.0f; }
    }
    __syncthreads();

    // ---- P1: embeddings, 2n x 4d tiles ----
    {
        const int np = t & 7;
        const int n0 = np * 2, n1 = n0 + 1;
        const int d0 = (t >> 3) * 4;

        float sa0[4], sa1[4], sp0[4], sp1[4];
        #pragma unroll
        for (int u = 0; u < 4; u++) { sa0[u] = 0.0f; sa1[u] = 0.0f; }
        #pragma unroll
        for (int k = 0; k < OBS; k += 4) {
            float4 x0 = *(const float4*)&st[n0 * ST_S + k];
            float4 x1 = *(const float4*)&st[n1 * ST_S + k];
            #pragma unroll
            for (int u = 0; u < 4; u++) {
                float4 wv = *(const float4*)&We[(d0 + u) * WE_S + k];
                sa0[u] = dot4(wv, x0, sa0[u]);
                sa1[u] = dot4(wv, x1, sa1[u]);
            }
        }
        #pragma unroll
        for (int u = 0; u < 4; u++) { sp0[u] = sa0[u]; sp1[u] = sa1[u]; }
        #pragma unroll
        for (int k = 0; k < ACT; k += 4) {
            float4 xa0 = *(const float4*)&ac[n0 * AC_S + k];
            float4 xa1 = *(const float4*)&ac[n1 * AC_S + k];
            float4 xp0 = *(const float4*)&po[n0 * AC_S + k];
            float4 xp1 = *(const float4*)&po[n1 * AC_S + k];
            #pragma unroll
            for (int u = 0; u < 4; u++) {
                float4 wv = *(const float4*)&We[(d0 + u) * WE_S + OBS + k];
                sa0[u] = dot4(wv, xa0, sa0[u]);
                sa1[u] = dot4(wv, xa1, sa1[u]);
                sp0[u] = dot4(wv, xp0, sp0[u]);
                sp1[u] = dot4(wv, xp1, sp1[u]);
            }
        }
        // attention-scalar partials
        float4 wsrc = *(const float4*)&Wa[d0];
        float4 wdst = *(const float4*)&Wa[DD + d0];
        float ps0, ps1, pd0, pd1;
        {
            float4 a0 = make_float4(sa0[0], sa0[1], sa0[2], sa0[3]);
            float4 a1 = make_float4(sa1[0], sa1[1], sa1[2], sa1[3]);
            ps0 = dot4(wsrc, a0, 0.0f); ps1 = dot4(wsrc, a1, 0.0f);
            pd0 = dot4(wdst, a0, 0.0f); pd1 = dot4(wdst, a1, 0.0f);
        }
        // tanh + delta, float4 stores
        {
            float4 t0, t1, dd0, dd1;
            t0.x = fast_tanh(sa0[0]); t0.y = fast_tanh(sa0[1]);
            t0.z = fast_tanh(sa0[2]); t0.w = fast_tanh(sa0[3]);
            t1.x = fast_tanh(sa1[0]); t1.y = fast_tanh(sa1[1]);
            t1.z = fast_tanh(sa1[2]); t1.w = fast_tanh(sa1[3]);
            dd0.x = fast_tanh(sp0[0]) - t0.x; dd0.y = fast_tanh(sp0[1]) - t0.y;
            dd0.z = fast_tanh(sp0[2]) - t0.z; dd0.w = fast_tanh(sp0[3]) - t0.w;
            dd1.x = fast_tanh(sp1[0]) - t1.x; dd1.y = fast_tanh(sp1[1]) - t1.y;
            dd1.z = fast_tanh(sp1[2]) - t1.z; dd1.w = fast_tanh(sp1[3]) - t1.w;
            *(float4*)&ta[n0 * E_S + d0] = t0;
            *(float4*)&ta[n1 * E_S + d0] = t1;
            *(float4*)&de[n0 * E_S + d0] = dd0;
            *(float4*)&de[n1 * E_S + d0] = dd1;
        }
        // reduce partials over the 4 lanes sharing np (lane, lane^8, lane^16, lane^24)
        ps0 += __shfl_xor_sync(0xffffffffu, ps0, 8);
        ps0 += __shfl_xor_sync(0xffffffffu, ps0, 16);
        ps1 += __shfl_xor_sync(0xffffffffu, ps1, 8);
        ps1 += __shfl_xor_sync(0xffffffffu, ps1, 16);
        pd0 += __shfl_xor_sync(0xffffffffu, pd0, 8);
        pd0 += __shfl_xor_sync(0xffffffffu, pd0, 16);
        pd1 += __shfl_xor_sync(0xffffffffu, pd1, 8);
        pd1 += __shfl_xor_sync(0xffffffffu, pd1, 16);
        if ((t & 31) < 8) {
            atomicAdd(&ssrc[n0], ps0);
            atomicAdd(&ssrc[n1], ps1);
            atomicAdd(&sdst[n0], pd0);
            atomicAdd(&sdst[n1], pd1);
        }
    }
    __syncthreads();

    // ---- P2: parallel softmax (all threads) + W1 float4 load ----
    {
        const int i = t >> 4, j = t & 15;
        float e = lrelu(ssrc[i] + sdst[j]);
        // reduce over the 16 lanes sharing i (j = lane&15)
        float mx = e;
        #pragma unroll
        for (int m = 8; m; m >>= 1)
            mx = fmaxf(mx, __shfl_xor_sync(0xffffffffu, mx, m));
        float ex = __expf(e - mx);
        float sum = ex;
        #pragma unroll
        for (int m = 8; m; m >>= 1)
            sum += __shfl_xor_sync(0xffffffffu, sum, m);
        float wv = __fdividef(ex, sum);
        w[i * WT_S + j] = wv;
        if (write_w)
            out[BB * NN * NN + b * NN * NN + t] = wv;
    }
    // W1: 64x192 = 3072 float4, 12 per thread (into union region)
    #pragma unroll
    for (int i = 0; i < 12; i++) {
        int e = (t + i * 256) * 4;
        int r = e / NF, c = e - r * NF;
        float4 v = *(const float4*)&g_W1[e];
        *(float4*)&W1[r * W1_S + c] = v;
    }
    __syncthreads();

    // ---- P3: T[n,h]=(W1d.ta[n])/16, V[n,h]=(W1d.de[n])/16, au=W1s.st[n] (regs) ----
    const int pn = t & 15, ph0 = (t >> 4) * 4;
    float au[4];
    {
        float at[4], av[4];
        #pragma unroll
        for (int u = 0; u < 4; u++) { at[u] = 0.0f; av[u] = 0.0f; au[u] = 0.0f; }
        #pragma unroll
        for (int k = 0; k < OBS; k += 4) {
            float4 x = *(const float4*)&st[pn * ST_S + k];
            #pragma unroll
            for (int u = 0; u < 4; u++) {
                float4 wv = *(const float4*)&W1[(ph0 + u) * W1_S + k];
                au[u] = dot4(wv, x, au[u]);
            }
        }
        #pragma unroll
        for (int d = 0; d < DD; d += 4) {
            float4 xt = *(const float4*)&ta[pn * E_S + d];
            float4 xd = *(const float4*)&de[pn * E_S + d];
            #pragma unroll
            for (int u = 0; u < 4; u++) {
                float4 wv = *(const float4*)&W1[(ph0 + u) * W1_S + OBS + d];
                at[u] = dot4(wv, xt, at[u]);
                av[u] = dot4(wv, xd, av[u]);
            }
        }
        const float invN = 1.0f / 16.0f;
        float4 tv, vv;
        tv.x = at[0] * invN; tv.y = at[1] * invN; tv.z = at[2] * invN; tv.w = at[3] * invN;
        vv.x = av[0] * invN; vv.y = av[1] * invN; vv.z = av[2] * invN; vv.w = av[3] * invN;
        *(float4*)&T[pn * HV_S + ph0] = tv;
        *(float4*)&V[pn * HV_S + ph0] = vv;
    }
    __syncthreads();

    // ---- P4a: U[n,h] = au + sum_j w[n,j] * T[j,h] ----
    {
        float acc[4];
        #pragma unroll
        for (int u = 0; u < 4; u++) acc[u] = au[u];
        #pragma unroll
        for (int j = 0; j < NN; j++) {
            float wv = w[pn * WT_S + j];
            float4 tv = *(const float4*)&T[j * HV_S + ph0];
            acc[0] = fmaf(wv, tv.x, acc[0]);
            acc[1] = fmaf(wv, tv.y, acc[1]);
            acc[2] = fmaf(wv, tv.z, acc[2]);
            acc[3] = fmaf(wv, tv.w, acc[3]);
        }
        float4 uv;
        uv.x = acc[0]; uv.y = acc[1]; uv.z = acc[2]; uv.w = acc[3];
        *(float4*)&U[pn * HV_S + ph0] = uv;
    }
    __syncthreads();

    // ---- P4b: value[b,i,j] = W2 . lrelu(U[i] + w[i,j]*V[j]) ----
    {
        const int i = t >> 4, j = t & 15;
        float wv = w[i * WT_S + j];
        float acc = 0.0f;
        #pragma unroll
        for (int h = 0; h < HH; h += 4) {
            float4 u4 = *(const float4*)&U[i * HV_S + h];
            float4 v4 = *(const float4*)&V[j * HV_S + h];
            float4 w2 = *(const float4*)&W2s[h];
            acc = fmaf(w2.x, lrelu(fmaf(wv, v4.x, u4.x)), acc);
            acc = fmaf(w2.y, lrelu(fmaf(wv, v4.y, u4.y)), acc);
            acc = fmaf(w2.z, lrelu(fmaf(wv, v4.z, u4.z)), acc);
            acc = fmaf(w2.w, lrelu(fmaf(wv, v4.w, u4.w)), acc);
        }
        out[b * NN * NN + t] = acc;
    }
}

extern "C" void kernel_launch(void* const* d_in, const int* in_sizes, int n_in,
                              void* d_out, int out_size) {
    const float* st = (const float*)d_in[0];
    const float* po = (const float*)d_in[1];
    const float* ac = (const float*)d_in[2];
    const float* We = (const float*)d_in[3];
    const float* Wa = (const float*)d_in[4];
    const float* W1 = (const float*)d_in[5];
    const float* W2 = (const float*)d_in[6];
    float* out = (float*)d_out;

    const int smem = SMEM_FLOATS * (int)sizeof(float);
    cudaFuncSetAttribute(gac_kernel, cudaFuncAttributeMaxDynamicSharedMemorySize, smem);

    int write_w = (out_size >= 2 * BB * NN * NN) ? 1 : 0;

    gac_kernel<<<BB, 256, smem>>>(st, po, ac, We, Wa, W1, W2, out, write_w);
}